// round 2
// baseline (speedup 1.0000x reference)
#include <cuda_runtime.h>
#include <cuda_bf16.h>

// CenterLoss collapses to a per-row gathered squared distance:
// loss = [ sum_b clip(||x_b - c_{l_b}||^2, 1e-12, 1e12) + B*(C-1)*1e-12 ] / B
//
// Inputs (metadata order): x [B, D] f32, labels [B] int32 (jax downcasts the
// declared int64 without x64 enabled), centers [C, D] f32. Output: scalar f32.

#define BATCH 4096
#define FEAT 512
#define NCLASSES 10000

__global__ void init_out_kernel(float* out) {
    // constant term from the (C-1) masked-off entries per row:
    // B * (C-1) * 1e-12 / B = (C-1) * 1e-12
    out[0] = (float)((double)(NCLASSES - 1) * 1e-12);
}

__global__ __launch_bounds__(128) void center_loss_kernel(
    const float* __restrict__ x,
    const int* __restrict__ labels,
    const float* __restrict__ centers,
    float* __restrict__ out)
{
    const int b = blockIdx.x;
    const int t = threadIdx.x;

    int lbl = labels[b];
    // defensive clamp: a bad index becomes a wrong answer, not a fault
    lbl = min(max(lbl, 0), NCLASSES - 1);

    // D = 512 floats = 128 float4; one float4 per thread
    const float4* xr = reinterpret_cast<const float4*>(x + (size_t)b * FEAT);
    const float4* cr = reinterpret_cast<const float4*>(centers + (size_t)lbl * FEAT);

    float4 xv = xr[t];
    float4 cv = cr[t];

    float d0 = xv.x - cv.x;
    float d1 = xv.y - cv.y;
    float d2 = xv.z - cv.z;
    float d3 = xv.w - cv.w;
    float s = d0 * d0 + d1 * d1 + d2 * d2 + d3 * d3;

    // warp reduce
    #pragma unroll
    for (int off = 16; off > 0; off >>= 1)
        s += __shfl_xor_sync(0xFFFFFFFFu, s, off);

    __shared__ float warp_sums[4];
    if ((t & 31) == 0) warp_sums[t >> 5] = s;
    __syncthreads();

    if (t == 0) {
        float d = warp_sums[0] + warp_sums[1] + warp_sums[2] + warp_sums[3];
        // faithful clamp of the true-class entry
        d = fminf(fmaxf(d, 1e-12f), 1e12f);
        atomicAdd(out, d * (1.0f / (float)BATCH));
    }
}

extern "C" void kernel_launch(void* const* d_in, const int* in_sizes, int n_in,
                              void* d_out, int out_size) {
    const float* x = (const float*)d_in[0];
    const int* labels = (const int*)d_in[1];
    const float* centers = (const float*)d_in[2];
    float* out = (float*)d_out;

    init_out_kernel<<<1, 1>>>(out);
    center_loss_kernel<<<BATCH, 128>>>(x, labels, centers, out);
}

// round 3
// speedup vs baseline: 1.4049x; 1.4049x over previous
#include <cuda_runtime.h>
#include <cuda_bf16.h>

// CenterLoss collapses to a per-row gathered squared distance:
// loss = [ sum_b clip(||x_b - c_{l_b}||^2, 1e-12, 1e12) + B*(C-1)*1e-12 ] / B
//
// Inputs: x [B, D] f32, labels [B] int32, centers [C, D] f32. Output: scalar f32.
//
// Layout: one warp per row, 8 warps per 256-thread block -> 512 blocks (one
// wave on 148 SMs). Each thread issues 8 independent float4 loads (MLP=8).
// Single kernel: last block to finish folds in the clip-constant and writes
// out, then resets the device scratch so the kernel is graph-replayable.

#define BATCH 4096
#define FEAT 512
#define NCLASSES 10000
#define ROWS_PER_BLOCK 8
#define NBLOCKS (BATCH / ROWS_PER_BLOCK)   // 512

__device__ float g_sum = 0.0f;
__device__ unsigned int g_count = 0;

__global__ __launch_bounds__(256) void center_loss_kernel(
    const float* __restrict__ x,
    const int* __restrict__ labels,
    const float* __restrict__ centers,
    float* __restrict__ out)
{
    const int tid  = threadIdx.x;
    const int warp = tid >> 5;
    const int lane = tid & 31;
    const int row  = blockIdx.x * ROWS_PER_BLOCK + warp;

    // label first (dependent chain head), clamped defensively
    int lbl = labels[row];
    lbl = min(max(lbl, 0), NCLASSES - 1);

    const float4* xr = reinterpret_cast<const float4*>(x + (size_t)row * FEAT);
    const float4* cr = reinterpret_cast<const float4*>(centers + (size_t)lbl * FEAT);

    // 512 floats = 128 float4 per row; 32 lanes x 4 chunks each.
    float4 xv[4], cv[4];
#pragma unroll
    for (int i = 0; i < 4; i++) xv[i] = xr[lane + 32 * i];
#pragma unroll
    for (int i = 0; i < 4; i++) cv[i] = cr[lane + 32 * i];

    float s = 0.0f;
#pragma unroll
    for (int i = 0; i < 4; i++) {
        float d0 = xv[i].x - cv[i].x;
        float d1 = xv[i].y - cv[i].y;
        float d2 = xv[i].z - cv[i].z;
        float d3 = xv[i].w - cv[i].w;
        s += d0 * d0 + d1 * d1 + d2 * d2 + d3 * d3;
    }

    // warp reduce
#pragma unroll
    for (int off = 16; off > 0; off >>= 1)
        s += __shfl_xor_sync(0xFFFFFFFFu, s, off);

    __shared__ float warp_sums[ROWS_PER_BLOCK];
    if (lane == 0) {
        // faithful per-entry clamp of the true-class distance
        warp_sums[warp] = fminf(fmaxf(s, 1e-12f), 1e12f);
    }
    __syncthreads();

    if (warp == 0) {
        float p = (lane < ROWS_PER_BLOCK) ? warp_sums[lane] : 0.0f;
#pragma unroll
        for (int off = 4; off > 0; off >>= 1)
            p += __shfl_xor_sync(0xFFFFFFFFu, p, off);

        if (lane == 0) {
            atomicAdd(&g_sum, p);
            __threadfence();
            unsigned done = atomicInc(&g_count, NBLOCKS - 1); // wraps to 0 on last
            if (done == NBLOCKS - 1) {
                float total = *((volatile float*)&g_sum);
                out[0] = total * (1.0f / (float)BATCH)
                       + (float)((double)(NCLASSES - 1) * 1e-12);
                g_sum = 0.0f;   // reset for next graph replay
                __threadfence();
            }
        }
    }
}

extern "C" void kernel_launch(void* const* d_in, const int* in_sizes, int n_in,
                              void* d_out, int out_size) {
    const float* x = (const float*)d_in[0];
    const int* labels = (const int*)d_in[1];
    const float* centers = (const float*)d_in[2];
    float* out = (float*)d_out;

    center_loss_kernel<<<NBLOCKS, 256>>>(x, labels, centers, out);
}

// round 4
// speedup vs baseline: 1.4615x; 1.0403x over previous
#include <cuda_runtime.h>
#include <cuda_bf16.h>

// CenterLoss collapses to per-row gathered squared distance:
// loss = [ sum_b clip(||x_b - c_{l_b}||^2, 1e-12, 1e12) + B*(C-1)*1e-12 ] / B
//
// Inputs: x [B, D] f32, labels [B] int32, centers [C, D] f32. Output: scalar f32.
//
// R4: 2 rows per warp to amortize the label->center serial epoch chain.
// Epoch 1: label int2 + 8 x-float4 per thread (both rows).
// Epoch 2: 8 c-float4 per thread (both rows).
// 256 blocks x 256 threads, single kernel, last-block writes the output.

#define BATCH 4096
#define FEAT 512
#define NCLASSES 10000
#define WARPS_PER_BLOCK 8
#define ROWS_PER_WARP 2
#define NBLOCKS (BATCH / (WARPS_PER_BLOCK * ROWS_PER_WARP))   // 256

__device__ float g_sum = 0.0f;
__device__ unsigned int g_count = 0;

__global__ __launch_bounds__(256) void center_loss_kernel(
    const float* __restrict__ x,
    const int* __restrict__ labels,
    const float* __restrict__ centers,
    float* __restrict__ out)
{
    const int tid  = threadIdx.x;
    const int warp = tid >> 5;
    const int lane = tid & 31;
    const int wg   = blockIdx.x * WARPS_PER_BLOCK + warp;   // 0..2047
    const int row0 = wg * ROWS_PER_WARP;                    // even -> int2 aligned

    // ---- epoch 1: labels (lane 0) + all x loads for both rows ----
    int2 lbl2 = make_int2(0, 0);
    if (lane == 0) lbl2 = *reinterpret_cast<const int2*>(labels + row0);

    const float4* xr0 = reinterpret_cast<const float4*>(x + (size_t)row0 * FEAT);
    const float4* xr1 = reinterpret_cast<const float4*>(x + (size_t)(row0 + 1) * FEAT);

    float4 xa[4], xb[4];
#pragma unroll
    for (int i = 0; i < 4; i++) xa[i] = xr0[lane + 32 * i];
#pragma unroll
    for (int i = 0; i < 4; i++) xb[i] = xr1[lane + 32 * i];

    // broadcast labels (warp stalls only on the label load here; x loads in flight)
    int l0 = __shfl_sync(0xFFFFFFFFu, lbl2.x, 0);
    int l1 = __shfl_sync(0xFFFFFFFFu, lbl2.y, 0);
    l0 = min(max(l0, 0), NCLASSES - 1);
    l1 = min(max(l1, 0), NCLASSES - 1);

    // ---- epoch 2: both rows' center loads ----
    const float4* cr0 = reinterpret_cast<const float4*>(centers + (size_t)l0 * FEAT);
    const float4* cr1 = reinterpret_cast<const float4*>(centers + (size_t)l1 * FEAT);

    float4 ca[4], cb[4];
#pragma unroll
    for (int i = 0; i < 4; i++) ca[i] = cr0[lane + 32 * i];
#pragma unroll
    for (int i = 0; i < 4; i++) cb[i] = cr1[lane + 32 * i];

    float s0 = 0.0f, s1 = 0.0f;
#pragma unroll
    for (int i = 0; i < 4; i++) {
        float d0 = xa[i].x - ca[i].x, d1 = xa[i].y - ca[i].y;
        float d2 = xa[i].z - ca[i].z, d3 = xa[i].w - ca[i].w;
        s0 += d0 * d0 + d1 * d1 + d2 * d2 + d3 * d3;
        float e0 = xb[i].x - cb[i].x, e1 = xb[i].y - cb[i].y;
        float e2 = xb[i].z - cb[i].z, e3 = xb[i].w - cb[i].w;
        s1 += e0 * e0 + e1 * e1 + e2 * e2 + e3 * e3;
    }

    // warp reduce both rows
#pragma unroll
    for (int off = 16; off > 0; off >>= 1) {
        s0 += __shfl_xor_sync(0xFFFFFFFFu, s0, off);
        s1 += __shfl_xor_sync(0xFFFFFFFFu, s1, off);
    }

    __shared__ float warp_sums[WARPS_PER_BLOCK];
    if (lane == 0) {
        // faithful per-entry clamp, applied per row BEFORE summation
        float c0 = fminf(fmaxf(s0, 1e-12f), 1e12f);
        float c1 = fminf(fmaxf(s1, 1e-12f), 1e12f);
        warp_sums[warp] = c0 + c1;
    }
    __syncthreads();

    if (warp == 0) {
        float p = (lane < WARPS_PER_BLOCK) ? warp_sums[lane] : 0.0f;
#pragma unroll
        for (int off = 4; off > 0; off >>= 1)
            p += __shfl_xor_sync(0xFFFFFFFFu, p, off);

        if (lane == 0) {
            atomicAdd(&g_sum, p);
            __threadfence();
            unsigned done = atomicInc(&g_count, NBLOCKS - 1); // wraps to 0 on last
            if (done == NBLOCKS - 1) {
                float total = *((volatile float*)&g_sum);
                out[0] = total * (1.0f / (float)BATCH)
                       + (float)((double)(NCLASSES - 1) * 1e-12);
                g_sum = 0.0f;   // reset for next graph replay
                __threadfence();
            }
        }
    }
}

extern "C" void kernel_launch(void* const* d_in, const int* in_sizes, int n_in,
                              void* d_out, int out_size) {
    const float* x = (const float*)d_in[0];
    const int* labels = (const int*)d_in[1];
    const float* centers = (const float*)d_in[2];
    float* out = (float*)d_out;

    center_loss_kernel<<<NBLOCKS, 256>>>(x, labels, centers, out);
}